// round 1
// baseline (speedup 1.0000x reference)
#include <cuda_runtime.h>

#define HDIM 128
#define WDIM 128
#define CDIM 256
#define AS_STRIDE 132
#define SMEM_FLOATS (128 * AS_STRIDE * 2)

extern __shared__ float smem_dyn[];

// ---------------------------------------------------------------------------
// Softmax of a 128x128 attention tile with Gaussian distance bias:
//   A[row][k] = softmax_k( attn[row][k] - (shift*(k-row)^2 + bias) )
// 8 warps, each warp handles 16 rows; 32 lanes x float4 covers 128 cols.
// ---------------------------------------------------------------------------
__device__ __forceinline__ void softmax_tile(const float* __restrict__ attn_base,
                                             float sh, float bi,
                                             float* __restrict__ As,
                                             int lane, int wid)
{
    #pragma unroll 1
    for (int rr = 0; rr < 16; ++rr) {
        int row = wid * 16 + rr;
        float4 v = *(const float4*)(attn_base + row * 128 + lane * 4);
        float fr = (float)row;
        float vv[4] = {v.x, v.y, v.z, v.w};
        #pragma unroll
        for (int j = 0; j < 4; ++j) {
            float d = (float)(lane * 4 + j) - fr;
            vv[j] -= fmaf(sh, d * d, bi);
        }
        float m = fmaxf(fmaxf(vv[0], vv[1]), fmaxf(vv[2], vv[3]));
        #pragma unroll
        for (int o = 16; o > 0; o >>= 1)
            m = fmaxf(m, __shfl_xor_sync(0xffffffffu, m, o));
        float e[4];
        float s = 0.f;
        #pragma unroll
        for (int j = 0; j < 4; ++j) { e[j] = __expf(vv[j] - m); s += e[j]; }
        #pragma unroll
        for (int o = 16; o > 0; o >>= 1)
            s += __shfl_xor_sync(0xffffffffu, s, o);
        float inv = 1.0f / s;
        float4 w = make_float4(e[0] * inv, e[1] * inv, e[2] * inv, e[3] * inv);
        *(float4*)(As + row * AS_STRIDE + lane * 4) = w;
    }
}

// ---------------------------------------------------------------------------
// 128x128x128 smem GEMM, 256 threads, 8x8 micro-tile per thread
// (4 quadrants of 4x4 at m = ty*4 / ty*4+64, n = tx*4 / tx*4+64).
// ---------------------------------------------------------------------------
__device__ __forceinline__ void gemm_128(const float* __restrict__ As,
                                         const float* __restrict__ Bs,
                                         float acc[8][8], int tx, int ty)
{
    const int m0 = ty * 4, m1 = m0 + 64;
    const int n0 = tx * 4, n1 = n0 + 64;
    #pragma unroll 8
    for (int kk = 0; kk < 128; ++kk) {
        float a[8];
        #pragma unroll
        for (int i = 0; i < 4; ++i) {
            a[i]     = As[(m0 + i) * AS_STRIDE + kk];
            a[4 + i] = As[(m1 + i) * AS_STRIDE + kk];
        }
        float4 b0 = *(const float4*)(Bs + kk * AS_STRIDE + n0);
        float4 b1 = *(const float4*)(Bs + kk * AS_STRIDE + n1);
        float bb[8] = {b0.x, b0.y, b0.z, b0.w, b1.x, b1.y, b1.z, b1.w};
        #pragma unroll
        for (int i = 0; i < 8; ++i)
            #pragma unroll
            for (int j = 0; j < 8; ++j)
                acc[i][j] = fmaf(a[i], bb[j], acc[i][j]);
    }
}

// ---------------------------------------------------------------------------
// Term 1: out[b,r,c,d] = sum_k softmax_k(attnx[b,r,c,k]+gx[c,k]) * V[b,r,k,d]
// CTA = (nh in {0,1} C-half, r, b). Writes out (full overwrite).
// ---------------------------------------------------------------------------
__global__ void __launch_bounds__(256) gt_term1(
    const float* __restrict__ attn, const float* __restrict__ V,
    const float* __restrict__ sp, const float* __restrict__ bp,
    float* __restrict__ out)
{
    float* As = smem_dyn;
    float* Bs = smem_dyn + 128 * AS_STRIDE;
    const int nh = blockIdx.x, r = blockIdx.y, b = blockIdx.z;
    const int t = threadIdx.x, lane = t & 31, wid = t >> 5;
    const float sh = sp[0], bi = bp[0];

    const float* attn_base = attn + (size_t)(b * HDIM + r) * (WDIM * WDIM);
    softmax_tile(attn_base, sh, bi, As, lane, wid);

    const float* vbase = V + (size_t)(b * HDIM + r) * (WDIM * CDIM) + nh * 128;
    for (int idx = t; idx < 128 * 32; idx += 256) {
        int row = idx >> 5;
        int c4  = (idx & 31) << 2;
        *(float4*)(Bs + row * AS_STRIDE + c4) =
            *(const float4*)(vbase + row * CDIM + c4);
    }
    __syncthreads();

    float acc[8][8];
    #pragma unroll
    for (int i = 0; i < 8; ++i)
        #pragma unroll
        for (int j = 0; j < 8; ++j) acc[i][j] = 0.f;

    const int tx = t & 15, ty = t >> 4;
    gemm_128(As, Bs, acc, tx, ty);

    float* obase = out + (size_t)(b * HDIM + r) * (WDIM * CDIM) + nh * 128;
    #pragma unroll
    for (int i = 0; i < 8; ++i) {
        int m = (i < 4) ? (ty * 4 + i) : (64 + ty * 4 + (i - 4));
        float4 v0 = make_float4(acc[i][0], acc[i][1], acc[i][2], acc[i][3]);
        float4 v1 = make_float4(acc[i][4], acc[i][5], acc[i][6], acc[i][7]);
        *(float4*)(obase + m * CDIM + tx * 4)      = v0;
        *(float4*)(obase + m * CDIM + 64 + tx * 4) = v1;
    }
}

// ---------------------------------------------------------------------------
// Term 2: out[b,r,c,d] += sum_k softmax_k(attny[b,c,r,k]+gy[r,k]) * V[b,k,c,d]
// CTA = (nh, c, b). V rows strided by W*C; out read-modify-write.
// ---------------------------------------------------------------------------
__global__ void __launch_bounds__(256) gt_term2(
    const float* __restrict__ attn, const float* __restrict__ V,
    const float* __restrict__ sp, const float* __restrict__ bp,
    float* __restrict__ out)
{
    float* As = smem_dyn;
    float* Bs = smem_dyn + 128 * AS_STRIDE;
    const int nh = blockIdx.x, c = blockIdx.y, b = blockIdx.z;
    const int t = threadIdx.x, lane = t & 31, wid = t >> 5;
    const float sh = sp[0], bi = bp[0];

    const float* attn_base = attn + (size_t)(b * WDIM + c) * (HDIM * HDIM);
    softmax_tile(attn_base, sh, bi, As, lane, wid);

    // V[b, k, c, nh*128 + d]: row k at stride W*C floats
    const float* vbase = V + (size_t)b * HDIM * WDIM * CDIM + (size_t)c * CDIM + nh * 128;
    for (int idx = t; idx < 128 * 32; idx += 256) {
        int row = idx >> 5;
        int c4  = (idx & 31) << 2;
        *(float4*)(Bs + row * AS_STRIDE + c4) =
            *(const float4*)(vbase + (size_t)row * (WDIM * CDIM) + c4);
    }
    __syncthreads();

    float acc[8][8];
    #pragma unroll
    for (int i = 0; i < 8; ++i)
        #pragma unroll
        for (int j = 0; j < 8; ++j) acc[i][j] = 0.f;

    const int tx = t & 15, ty = t >> 4;
    gemm_128(As, Bs, acc, tx, ty);

    // out[b, m, c, nh*128 + n]: row m at stride W*C floats; accumulate.
    float* obase = out + (size_t)b * HDIM * WDIM * CDIM + (size_t)c * CDIM + nh * 128;
    #pragma unroll
    for (int i = 0; i < 8; ++i) {
        int m = (i < 4) ? (ty * 4 + i) : (64 + ty * 4 + (i - 4));
        float* op0 = obase + (size_t)m * (WDIM * CDIM) + tx * 4;
        float* op1 = op0 + 64;
        float4 cur0 = *(float4*)op0;
        float4 cur1 = *(float4*)op1;
        cur0.x += acc[i][0]; cur0.y += acc[i][1]; cur0.z += acc[i][2]; cur0.w += acc[i][3];
        cur1.x += acc[i][4]; cur1.y += acc[i][5]; cur1.z += acc[i][6]; cur1.w += acc[i][7];
        *(float4*)op0 = cur0;
        *(float4*)op1 = cur1;
    }
}

// ---------------------------------------------------------------------------
// Launch
// Inputs (metadata order): 0:x (unused), 1:atten_x_full, 2:atten_y_full,
//                          3:value_full, 4:shift, 5:bias
// ---------------------------------------------------------------------------
extern "C" void kernel_launch(void* const* d_in, const int* in_sizes, int n_in,
                              void* d_out, int out_size)
{
    const float* attn_x = (const float*)d_in[1];
    const float* attn_y = (const float*)d_in[2];
    const float* V      = (const float*)d_in[3];
    const float* sh     = (const float*)d_in[4];
    const float* bi     = (const float*)d_in[5];
    float* out          = (float*)d_out;

    const int B = in_sizes[3] / (HDIM * WDIM * CDIM);

    const size_t smem_bytes = SMEM_FLOATS * sizeof(float);
    cudaFuncSetAttribute(gt_term1, cudaFuncAttributeMaxDynamicSharedMemorySize, (int)smem_bytes);
    cudaFuncSetAttribute(gt_term2, cudaFuncAttributeMaxDynamicSharedMemorySize, (int)smem_bytes);

    dim3 grid(2, 128, B);
    dim3 blk(256);
    gt_term1<<<grid, blk, smem_bytes>>>(attn_x, V, sh, bi, out);
    gt_term2<<<grid, blk, smem_bytes>>>(attn_y, V, sh, bi, out);
}

// round 3
// speedup vs baseline: 2.1236x; 2.1236x over previous
#include <cuda_runtime.h>
#include <cstdint>

#define HDIM 128
#define WDIM 128
#define CDIM 256

#define A_STRIDE 132            // words, pad for conflict-free frag loads
#define B_STRIDE 260
#define SMEM_WORDS (128 * A_STRIDE + 128 * B_STRIDE)
#define SMEM_BYTES (SMEM_WORDS * 4)

static __device__ __forceinline__ uint32_t tf32u(float x) {
    uint32_t r;
    asm("cvt.rna.tf32.f32 %0, %1;" : "=r"(r) : "f"(x));
    return r;
}

static __device__ __forceinline__ void mma_tf32(float c[4], uint32_t a0, uint32_t a1,
                                                uint32_t a2, uint32_t a3,
                                                uint32_t b0, uint32_t b1) {
    asm volatile(
        "mma.sync.aligned.m16n8k8.row.col.f32.tf32.tf32.f32 "
        "{%0,%1,%2,%3}, {%4,%5,%6,%7}, {%8,%9}, {%0,%1,%2,%3};"
        : "+f"(c[0]), "+f"(c[1]), "+f"(c[2]), "+f"(c[3])
        : "r"(a0), "r"(a1), "r"(a2), "r"(a3), "r"(b0), "r"(b1));
}

// ---------------------------------------------------------------------------
// One CTA computes D[128,256] = softmax(attn_tile + gauss) @ Vtile, for one
// (b, rc). term=0: V rows stride CDIM, overwrite out. term=1: V rows stride
// W*CDIM, accumulate into out.
// 8 warps; warp w computes 64x64 slab: rows (w&1)*64.., cols (w>>1)*64..
// ---------------------------------------------------------------------------
__global__ void __launch_bounds__(256, 1) gt_mma(
    const float* __restrict__ attn, const float* __restrict__ V,
    const float* __restrict__ sp, const float* __restrict__ bp,
    float* __restrict__ out, int term)
{
    extern __shared__ uint32_t smem[];
    uint32_t* As = smem;                         // [128][132] tf32 bits
    uint32_t* Bs = smem + 128 * A_STRIDE;        // [128 k][260 d] tf32 bits

    const int tid = threadIdx.x, lane = tid & 31, wid = tid >> 5;
    const int rc = blockIdx.x, b = blockIdx.y;
    const float sh = sp[0], bi = bp[0];

    // ---- softmax rows -> As ----
    const float* abase = attn + ((size_t)b * 128 + rc) * (size_t)(128 * 128);
    #pragma unroll 1
    for (int rr = 0; rr < 16; ++rr) {
        int row = wid * 16 + rr;
        float4 v = __ldg((const float4*)(abase + row * 128 + lane * 4));
        float vv[4] = {v.x, v.y, v.z, v.w};
        float fr = (float)row;
        #pragma unroll
        for (int j = 0; j < 4; ++j) {
            float d = (float)(lane * 4 + j) - fr;
            vv[j] -= fmaf(sh, d * d, bi);
        }
        float m = fmaxf(fmaxf(vv[0], vv[1]), fmaxf(vv[2], vv[3]));
        #pragma unroll
        for (int o = 16; o > 0; o >>= 1) m = fmaxf(m, __shfl_xor_sync(~0u, m, o));
        float e[4]; float s = 0.f;
        #pragma unroll
        for (int j = 0; j < 4; ++j) { e[j] = __expf(vv[j] - m); s += e[j]; }
        #pragma unroll
        for (int o = 16; o > 0; o >>= 1) s += __shfl_xor_sync(~0u, s, o);
        float inv = 1.0f / s;
        uint4 w = make_uint4(tf32u(e[0] * inv), tf32u(e[1] * inv),
                             tf32u(e[2] * inv), tf32u(e[3] * inv));
        *(uint4*)(As + row * A_STRIDE + lane * 4) = w;
    }

    // ---- V tile [128 k][256 d] -> Bs (tf32 bits) ----
    const size_t vstride = term ? (size_t)(WDIM * CDIM) : (size_t)CDIM;
    const size_t tile_off = term ? ((size_t)b * HDIM * WDIM * CDIM + (size_t)rc * CDIM)
                                 : ((size_t)b * 128 + rc) * (size_t)(WDIM * CDIM);
    const float* vbase = V + tile_off;

    #pragma unroll 4
    for (int i = 0; i < 32; ++i) {
        int idx = i * 256 + tid;         // 0..8191 float4 slots
        int k = idx >> 6;                // row 0..127
        int q = idx & 63;                // float4 within row
        float4 f = __ldg((const float4*)(vbase + (size_t)k * vstride + q * 4));
        uint4 w = make_uint4(tf32u(f.x), tf32u(f.y), tf32u(f.z), tf32u(f.w));
        *(uint4*)(Bs + k * B_STRIDE + q * 4) = w;
    }

    __syncthreads();

    // ---- mma: each warp 64x64 slab (4 m16 tiles x 8 n8 tiles, 16 k8 steps) ----
    const int mh = (wid & 1) * 64;
    const int nq = (wid >> 1) * 64;
    const int lr = lane >> 2;            // 0..7
    const int lc = lane & 3;             // 0..3

    float acc[4][8][4];
    #pragma unroll
    for (int t = 0; t < 4; ++t)
        #pragma unroll
        for (int j = 0; j < 8; ++j)
            #pragma unroll
            for (int q = 0; q < 4; ++q) acc[t][j][q] = 0.f;

    #pragma unroll 1
    for (int ks = 0; ks < 16; ++ks) {
        const int kc = ks * 8;
        uint32_t a[4][4];
        #pragma unroll
        for (int t = 0; t < 4; ++t) {
            const uint32_t* ap = As + (mh + t * 16 + lr) * A_STRIDE + kc + lc;
            a[t][0] = ap[0];
            a[t][1] = ap[8 * A_STRIDE];
            a[t][2] = ap[4];
            a[t][3] = ap[8 * A_STRIDE + 4];
        }
        #pragma unroll
        for (int j = 0; j < 8; ++j) {
            const uint32_t* bp8 = Bs + (kc + lc) * B_STRIDE + nq + j * 8 + lr;
            uint32_t b0 = bp8[0];
            uint32_t b1 = bp8[4 * B_STRIDE];
            #pragma unroll
            for (int t = 0; t < 4; ++t)
                mma_tf32(acc[t][j], a[t][0], a[t][1], a[t][2], a[t][3], b0, b1);
        }
    }

    // ---- epilogue: direct float2 stores (32B-sector aligned per lane quad) ----
    float* obase = out + tile_off;
    const size_t ostride = vstride;
    #pragma unroll
    for (int t = 0; t < 4; ++t) {
        #pragma unroll
        for (int j = 0; j < 8; ++j) {
            int r0 = mh + t * 16 + lr;
            int col = nq + j * 8 + lc * 2;
            float* p0 = obase + (size_t)r0 * ostride + col;
            float* p1 = p0 + 8 * ostride;
            float2 v0 = make_float2(acc[t][j][0], acc[t][j][1]);
            float2 v1 = make_float2(acc[t][j][2], acc[t][j][3]);
            if (term) {
                float2 c0 = *(float2*)p0, c1 = *(float2*)p1;
                v0.x += c0.x; v0.y += c0.y;
                v1.x += c1.x; v1.y += c1.y;
            }
            *(float2*)p0 = v0;
            *(float2*)p1 = v1;
        }
    }
}

extern "C" void kernel_launch(void* const* d_in, const int* in_sizes, int n_in,
                              void* d_out, int out_size)
{
    const float* attn_x = (const float*)d_in[1];
    const float* attn_y = (const float*)d_in[2];
    const float* V      = (const float*)d_in[3];
    const float* sh     = (const float*)d_in[4];
    const float* bi     = (const float*)d_in[5];
    float* out          = (float*)d_out;

    const int B = in_sizes[3] / (HDIM * WDIM * CDIM);

    cudaFuncSetAttribute(gt_mma, cudaFuncAttributeMaxDynamicSharedMemorySize, SMEM_BYTES);

    dim3 grid(128, B);
    gt_mma<<<grid, 256, SMEM_BYTES>>>(attn_x, V, sh, bi, out, 0);
    gt_mma<<<grid, 256, SMEM_BYTES>>>(attn_y, V, sh, bi, out, 1);
}

// round 4
// speedup vs baseline: 3.0766x; 1.4488x over previous
#include <cuda_runtime.h>
#include <cstdint>

#define HDIM 128
#define WDIM 128
#define CDIM 256

#define A_STRIDE 132            // words; A frag banks = lr*4+lc, bijective -> conflict-free
#define B_STRIDE 264            // words; B frag banks = lc*8+lr, bijective -> conflict-free
#define SMEM_BYTES (128 * A_STRIDE * 4 + 128 * B_STRIDE * 4)   // 67584 + 135168 = 202752

static __device__ __forceinline__ uint32_t tf32u(float x) {
    uint32_t r;
    asm("cvt.rna.tf32.f32 %0, %1;" : "=r"(r) : "f"(x));
    return r;
}

static __device__ __forceinline__ void cp16(uint32_t dst, const void* src) {
    asm volatile("cp.async.ca.shared.global [%0], [%1], 16;" :: "r"(dst), "l"(src));
}

static __device__ __forceinline__ void mma_tf32(float c[4], uint32_t a0, uint32_t a1,
                                                uint32_t a2, uint32_t a3,
                                                uint32_t b0, uint32_t b1) {
    asm volatile(
        "mma.sync.aligned.m16n8k8.row.col.f32.tf32.tf32.f32 "
        "{%0,%1,%2,%3}, {%4,%5,%6,%7}, {%8,%9}, {%0,%1,%2,%3};"
        : "+f"(c[0]), "+f"(c[1]), "+f"(c[2]), "+f"(c[3])
        : "r"(a0), "r"(a1), "r"(a2), "r"(a3), "r"(b0), "r"(b1));
}

// ---------------------------------------------------------------------------
// CTA = one (b, rc): D[128,256] = softmax(attn+gauss) @ Vtile.
// 16 warps; warp w -> 64x32 slab: rows (w&1)*64.., cols (w>>1)*32..
// term=0: V/out row stride CDIM, overwrite. term=1: stride W*CDIM, accumulate.
// ---------------------------------------------------------------------------
__global__ void __launch_bounds__(512, 1) gt_mma(
    const float* __restrict__ attn, const float* __restrict__ V,
    const float* __restrict__ sp, const float* __restrict__ bp,
    float* __restrict__ out, int term)
{
    extern __shared__ uint32_t smem[];
    uint32_t* As = smem;                          // raw attn -> softmaxed tf32, [128][132]
    uint32_t* Bs = smem + 128 * A_STRIDE;         // raw V fp32, [128 k][264]
    const uint32_t As_u = (uint32_t)__cvta_generic_to_shared(As);
    const uint32_t Bs_u = (uint32_t)__cvta_generic_to_shared(Bs);

    const int tid = threadIdx.x, lane = tid & 31, wid = tid >> 5;
    const int rc = blockIdx.x, b = blockIdx.y;
    const float sh = sp[0], bi = bp[0];

    const float* abase = attn + ((size_t)b * 128 + rc) * (size_t)(128 * 128);
    const size_t vstride = term ? (size_t)(WDIM * CDIM) : (size_t)CDIM;
    const size_t tile_off = term ? ((size_t)b * HDIM * WDIM * CDIM + (size_t)rc * CDIM)
                                 : ((size_t)b * 128 + rc) * (size_t)(WDIM * CDIM);
    const float* vbase = V + tile_off;

    // ---- async loads: attn tile (group A), V tile (group B) ----
    #pragma unroll
    for (int i = 0; i < 8; ++i) {                 // 4096 16B chunks of attn
        int c = i * 512 + tid;
        int row = c >> 5, q = c & 31;
        cp16(As_u + (uint32_t)row * (A_STRIDE * 4) + (uint32_t)q * 16,
             abase + row * 128 + q * 4);
    }
    asm volatile("cp.async.commit_group;" ::: "memory");
    #pragma unroll
    for (int i = 0; i < 16; ++i) {                // 8192 16B chunks of V
        int c = i * 512 + tid;
        int row = c >> 6, q = c & 63;
        cp16(Bs_u + (uint32_t)row * (B_STRIDE * 4) + (uint32_t)q * 16,
             vbase + (size_t)row * vstride + q * 4);
    }
    asm volatile("cp.async.commit_group;" ::: "memory");

    // ---- softmax (attn arrived; V still in flight) ----
    asm volatile("cp.async.wait_group 1;" ::: "memory");
    __syncthreads();

    #pragma unroll 1
    for (int rr = 0; rr < 8; ++rr) {
        int row = wid * 8 + rr;
        float4 v = *(const float4*)((const float*)As + row * A_STRIDE + lane * 4);
        float vv[4] = {v.x, v.y, v.z, v.w};
        float fr = (float)row;
        #pragma unroll
        for (int j = 0; j < 4; ++j) {
            float d = (float)(lane * 4 + j) - fr;
            vv[j] -= fmaf(sh, d * d, bi);
        }
        float m = fmaxf(fmaxf(vv[0], vv[1]), fmaxf(vv[2], vv[3]));
        #pragma unroll
        for (int o = 16; o > 0; o >>= 1) m = fmaxf(m, __shfl_xor_sync(~0u, m, o));
        float e[4]; float s = 0.f;
        #pragma unroll
        for (int j = 0; j < 4; ++j) { e[j] = __expf(vv[j] - m); s += e[j]; }
        #pragma unroll
        for (int o = 16; o > 0; o >>= 1) s += __shfl_xor_sync(~0u, s, o);
        float inv = 1.0f / s;
        uint4 w = make_uint4(tf32u(e[0] * inv), tf32u(e[1] * inv),
                             tf32u(e[2] * inv), tf32u(e[3] * inv));
        *(uint4*)(As + row * A_STRIDE + lane * 4) = w;
    }

    asm volatile("cp.async.wait_group 0;" ::: "memory");
    __syncthreads();

    // ---- MMA: warp slab 64x32 = 4 m16 tiles x 4 n8 tiles, 16 k8 steps ----
    const int mh = (wid & 1) * 64;
    const int nq = (wid >> 1) * 32;
    const int lr = lane >> 2;             // 0..7
    const int lc = lane & 3;              // 0..3

    float acc[4][4][4];
    #pragma unroll
    for (int t = 0; t < 4; ++t)
        #pragma unroll
        for (int j = 0; j < 4; ++j)
            #pragma unroll
            for (int q = 0; q < 4; ++q) acc[t][j][q] = 0.f;

    #pragma unroll 2
    for (int ks = 0; ks < 16; ++ks) {
        const int kc = ks * 8;
        uint32_t a[4][4];
        #pragma unroll
        for (int t = 0; t < 4; ++t) {
            const uint32_t* ap = As + (mh + t * 16 + lr) * A_STRIDE + kc + lc;
            a[t][0] = ap[0];
            a[t][1] = ap[8 * A_STRIDE];
            a[t][2] = ap[4];
            a[t][3] = ap[8 * A_STRIDE + 4];
        }
        #pragma unroll
        for (int j = 0; j < 4; ++j) {
            const float* bp8 = (const float*)Bs + (kc + lc) * B_STRIDE + nq + j * 8 + lr;
            uint32_t b0 = tf32u(bp8[0]);
            uint32_t b1 = tf32u(bp8[4 * B_STRIDE]);
            #pragma unroll
            for (int t = 0; t < 4; ++t)
                mma_tf32(acc[t][j], a[t][0], a[t][1], a[t][2], a[t][3], b0, b1);
        }
    }

    // ---- epilogue ----
    float* obase = out + tile_off;
    const size_t ostride = vstride;
    #pragma unroll
    for (int t = 0; t < 4; ++t) {
        #pragma unroll
        for (int j = 0; j < 4; ++j) {
            int r0 = mh + t * 16 + lr;
            int col = nq + j * 8 + lc * 2;
            float* p0 = obase + (size_t)r0 * ostride + col;
            float* p1 = p0 + 8 * ostride;
            float2 v0 = make_float2(acc[t][j][0], acc[t][j][1]);
            float2 v1 = make_float2(acc[t][j][2], acc[t][j][3]);
            if (term) {
                float2 c0 = *(float2*)p0, c1 = *(float2*)p1;
                v0.x += c0.x; v0.y += c0.y;
                v1.x += c1.x; v1.y += c1.y;
            }
            *(float2*)p0 = v0;
            *(float2*)p1 = v1;
        }
    }
}

extern "C" void kernel_launch(void* const* d_in, const int* in_sizes, int n_in,
                              void* d_out, int out_size)
{
    const float* attn_x = (const float*)d_in[1];
    const float* attn_y = (const float*)d_in[2];
    const float* V      = (const float*)d_in[3];
    const float* sh     = (const float*)d_in[4];
    const float* bi     = (const float*)d_in[5];
    float* out          = (float*)d_out;

    const int B = in_sizes[3] / (HDIM * WDIM * CDIM);

    cudaFuncSetAttribute(gt_mma, cudaFuncAttributeMaxDynamicSharedMemorySize, SMEM_BYTES);

    dim3 grid(128, B);
    gt_mma<<<grid, 512, SMEM_BYTES>>>(attn_x, V, sh, bi, out, 0);
    gt_mma<<<grid, 512, SMEM_BYTES>>>(attn_y, V, sh, bi, out, 1);
}